// round 8
// baseline (speedup 1.0000x reference)
#include <cuda_runtime.h>

// 9x9 zero-padded box filter, 128 independent 512x512 fp32 images.
// Row pipeline over HALF-WIDTH bands: CTA = 256-wide x TH-row band.
// Vertical 9-sum slides in registers; horizontal 9-sum via smem ring.
// 96 threads: t<64 own the 64 float4 column groups of the half,
// t=64/65 compute the one-float4 halo group on each side, t>=66 idle.
// 2048 fine-grained CTAs (~1.15 waves) to flatten the single-wave tail
// that capped DRAM busy at 72% in the full-width version.

#define W   512
#define H   512
#define TH  64                  // rows per CTA band
#define NT  96
#define W4  (W / 4)             // 128 float4 groups per full row

__global__ __launch_bounds__(NT) void box9_kernel(const float* __restrict__ xin,
                                                  float* __restrict__ outp) {
    // 4 row-slots, 66 groups each: slot[j] = vsum of global group g0-1+j.
    __shared__ __align__(16) float4 buf[4][66];

    const int t  = threadIdx.x;
    const int hh = blockIdx.x & 1;            // width half: 0 or 1
    const int y0 = (blockIdx.x >> 1) * TH;
    const int g0 = hh * 64;                   // first own group of this half
    const size_t imgoff = (size_t)blockIdx.y * (W * H);
    const float4* __restrict__ base  = reinterpret_cast<const float4*>(xin + imgoff);
    float4* __restrict__       obase = reinterpret_cast<float4*>(outp + imgoff);

    const float4 z4 = make_float4(0.f, 0.f, 0.f, 0.f);
    const bool writer = (t < 64);

    // group assignment
    int g = 0; int slot = 0; bool active = false;
    if (t < 64)       { g = g0 + t;  slot = t + 1; active = true; }
    else if (t == 64) { g = g0 - 1;  slot = 0;     active = (hh == 1); }
    else if (t == 65) { g = g0 + 64; slot = 65;    active = (hh == 0); }
    const bool has_slot = (t < 66);
    if (!active) g = 0;                        // never dereferenced, keep valid

    // ---- prologue: vs = sum of input rows [y0-5, y0+3] (zeros outside) ----
    float4 vs = z4;
    if (active) {
        #pragma unroll
        for (int i = -5; i <= 3; i++) {
            int r = y0 + i;
            if ((unsigned)r < (unsigned)H) {
                float4 v = base[r * W4 + g];
                vs.x += v.x; vs.y += v.y; vs.z += v.z; vs.w += v.w;
            }
        }
    }

    // prefetch for first iteration (output rows y0, y0+1): n=x[y+4], o=x[y-5]
    float4 n0 = z4, o0 = z4, n1 = z4, o1 = z4;
    if (active) {
        int r;
        r = y0 + 4; if ((unsigned)r < (unsigned)H) n0 = base[r * W4 + g];
        r = y0 - 5; if ((unsigned)r < (unsigned)H) o0 = base[r * W4 + g];
        r = y0 + 5; if ((unsigned)r < (unsigned)H) n1 = base[r * W4 + g];
        r = y0 - 4; if ((unsigned)r < (unsigned)H) o1 = base[r * W4 + g];
    }

    #pragma unroll 2
    for (int k = 0; k < TH / 2; k++) {
        const int y = y0 + 2 * k;
        float4 na = n0, oa = o0, nb = n1, ob = o1;

        // prefetch for next iteration (output rows y+2, y+3)
        if (active && k + 1 < TH / 2) {
            int r;
            n0 = z4; o0 = z4; n1 = z4; o1 = z4;
            r = y + 6; if ((unsigned)r < (unsigned)H) n0 = base[r * W4 + g];
            r = y - 3; if ((unsigned)r < (unsigned)H) o0 = base[r * W4 + g];
            r = y + 7; if ((unsigned)r < (unsigned)H) n1 = base[r * W4 + g];
            r = y - 2; if ((unsigned)r < (unsigned)H) o1 = base[r * W4 + g];
        }

        // vertical slide, two rows (inactive threads keep vs = 0)
        vs.x += na.x - oa.x; vs.y += na.y - oa.y;
        vs.z += na.z - oa.z; vs.w += na.w - oa.w;
        float4 vs0 = vs;
        if (has_slot) buf[(2 * k) & 3][slot] = vs0;

        vs.x += nb.x - ob.x; vs.y += nb.y - ob.y;
        vs.z += nb.z - ob.z; vs.w += nb.w - ob.w;
        float4 vs1 = vs;
        if (has_slot) buf[(2 * k + 1) & 3][slot] = vs1;

        __syncthreads();

        if (writer) {
            // horizontal slide, row y
            {
                float4 a = buf[(2 * k) & 3][t];
                float4 c = buf[(2 * k) & 3][t + 2];
                float sb = (vs0.x + vs0.y) + (vs0.z + vs0.w);
                float sa = (a.x + a.y) + (a.z + a.w);
                float h0 = sa + sb + c.x;
                float h1 = h0 - a.x + c.y;
                float h2 = h1 - a.y + c.z;
                float h3 = h2 - a.z + c.w;
                __stcs(&obase[y * W4 + g0 + t], make_float4(h0, h1, h2, h3));
            }
            // horizontal slide, row y+1
            {
                float4 a = buf[(2 * k + 1) & 3][t];
                float4 c = buf[(2 * k + 1) & 3][t + 2];
                float sb = (vs1.x + vs1.y) + (vs1.z + vs1.w);
                float sa = (a.x + a.y) + (a.z + a.w);
                float h0 = sa + sb + c.x;
                float h1 = h0 - a.x + c.y;
                float h2 = h1 - a.y + c.z;
                float h3 = h2 - a.z + c.w;
                __stcs(&obase[(y + 1) * W4 + g0 + t], make_float4(h0, h1, h2, h3));
            }
        }
    }
}

extern "C" void kernel_launch(void* const* d_in, const int* in_sizes, int n_in,
                              void* d_out, int out_size) {
    const float* x = (const float*)d_in[0];
    float* out = (float*)d_out;
    int nimg = in_sizes[0] / (W * H);       // 128
    dim3 grid((H / TH) * 2, nimg);          // (16, 128) = 2048 CTAs
    box9_kernel<<<grid, NT>>>(x, out);
}

// round 9
// speedup vs baseline: 1.2331x; 1.2331x over previous
#include <cuda_runtime.h>

// 9x9 zero-padded box filter, 128 independent 512x512 fp32 images.
// Full-width row pipeline: CTA = 512-wide x TH-row band (measured optimum).
// Vertical 9-sum slides in registers, horizontal 9-sum via smem ring.
// R9: prefetch distance 2 (MLP 8 float4-loads in flight per thread),
// __ldcs on last-use old rows, __stcs streaming output stores.

#define W   512
#define H   512
#define TH  64                  // rows per CTA band
#define NT  128                 // one thread per float4 column group (512/4)
#define W4  (W / 4)             // 128

__device__ __forceinline__ float4 ld4(const float4* p) { return *p; }

__global__ __launch_bounds__(NT, 7)
void box9_kernel(const float* __restrict__ xin, float* __restrict__ outp) {
    // 4 row-slots: 2 rows in flight per barrier, alternating pairs.
    __shared__ __align__(16) float4 buf[4][132];

    const int t  = threadIdx.x;
    const int y0 = blockIdx.x * TH;
    const size_t imgoff = (size_t)blockIdx.y * (W * H);
    const float4* __restrict__ base  = reinterpret_cast<const float4*>(xin + imgoff);
    float4* __restrict__       obase = reinterpret_cast<float4*>(outp + imgoff);

    const float4 z4 = make_float4(0.f, 0.f, 0.f, 0.f);
    if (t < 4) {
        buf[t][0]   = z4;
        buf[t][129] = z4;
    }

    // ---- prologue: vs = sum of input rows [y0-5, y0+3] (zeros outside) ----
    // Invariant before the slide at output row y: vs = sum rows [y-5, y+3].
    float4 vs = z4;
    #pragma unroll
    for (int i = -5; i <= 3; i++) {
        int r = y0 + i;
        if ((unsigned)r < (unsigned)H) {
            float4 v = base[r * W4 + t];
            vs.x += v.x; vs.y += v.y; vs.z += v.z; vs.w += v.w;
        }
    }

    // Software pipeline, distance 2. Iteration k consumes rows
    // n=x[y+4], o=x[y-5] for y = y0+2k and y0+2k+1.
    // A* holds iteration k's rows, B* holds iteration k+1's rows.
    float4 An0 = z4, Ao0 = z4, An1 = z4, Ao1 = z4;
    float4 Bn0 = z4, Bo0 = z4, Bn1 = z4, Bo1 = z4;
    { int r;
      r = y0 + 4; if ((unsigned)r < (unsigned)H) An0 = base[r * W4 + t];
      r = y0 - 5; if ((unsigned)r < (unsigned)H) Ao0 = __ldcs(&base[r * W4 + t]);
      r = y0 + 5; if ((unsigned)r < (unsigned)H) An1 = base[r * W4 + t];
      r = y0 - 4; if ((unsigned)r < (unsigned)H) Ao1 = __ldcs(&base[r * W4 + t]);
      r = y0 + 6; if ((unsigned)r < (unsigned)H) Bn0 = base[r * W4 + t];
      r = y0 - 3; if ((unsigned)r < (unsigned)H) Bo0 = __ldcs(&base[r * W4 + t]);
      r = y0 + 7; if ((unsigned)r < (unsigned)H) Bn1 = base[r * W4 + t];
      r = y0 - 2; if ((unsigned)r < (unsigned)H) Bo1 = __ldcs(&base[r * W4 + t]);
    }

    #pragma unroll 2
    for (int k = 0; k < TH / 2; k++) {
        const int y = y0 + 2 * k;
        float4 na = An0, oa = Ao0, nb = An1, ob = Ao1;
        An0 = Bn0; Ao0 = Bo0; An1 = Bn1; Ao1 = Bo1;

        // issue loads for iteration k+2 (output rows y+4, y+5)
        if (k + 2 < TH / 2) {
            int r;
            Bn0 = z4; Bo0 = z4; Bn1 = z4; Bo1 = z4;
            r = y + 8; if ((unsigned)r < (unsigned)H) Bn0 = base[r * W4 + t];
            r = y - 1; if ((unsigned)r < (unsigned)H) Bo0 = __ldcs(&base[r * W4 + t]);
            r = y + 9; if ((unsigned)r < (unsigned)H) Bn1 = base[r * W4 + t];
            r = y    ; /* y >= 0 always */           Bo1 = __ldcs(&base[r * W4 + t]);
        }

        // vertical slide, two rows
        vs.x += na.x - oa.x; vs.y += na.y - oa.y;
        vs.z += na.z - oa.z; vs.w += na.w - oa.w;
        float4 vs0 = vs;
        buf[(2 * k) & 3][t + 1] = vs0;

        vs.x += nb.x - ob.x; vs.y += nb.y - ob.y;
        vs.z += nb.z - ob.z; vs.w += nb.w - ob.w;
        float4 vs1 = vs;
        buf[(2 * k + 1) & 3][t + 1] = vs1;

        __syncthreads();

        // horizontal slide, row y
        {
            float4 a = buf[(2 * k) & 3][t];
            float4 c = buf[(2 * k) & 3][t + 2];
            float sb = (vs0.x + vs0.y) + (vs0.z + vs0.w);
            float sa = (a.x + a.y) + (a.z + a.w);
            float h0 = sa + sb + c.x;
            float h1 = h0 - a.x + c.y;
            float h2 = h1 - a.y + c.z;
            float h3 = h2 - a.z + c.w;
            __stcs(&obase[y * W4 + t], make_float4(h0, h1, h2, h3));
        }
        // horizontal slide, row y+1
        {
            float4 a = buf[(2 * k + 1) & 3][t];
            float4 c = buf[(2 * k + 1) & 3][t + 2];
            float sb = (vs1.x + vs1.y) + (vs1.z + vs1.w);
            float sa = (a.x + a.y) + (a.z + a.w);
            float h0 = sa + sb + c.x;
            float h1 = h0 - a.x + c.y;
            float h2 = h1 - a.y + c.z;
            float h3 = h2 - a.z + c.w;
            __stcs(&obase[(y + 1) * W4 + t], make_float4(h0, h1, h2, h3));
        }
    }
}

extern "C" void kernel_launch(void* const* d_in, const int* in_sizes, int n_in,
                              void* d_out, int out_size) {
    const float* x = (const float*)d_in[0];
    float* out = (float*)d_out;
    int nimg = in_sizes[0] / (W * H);     // 128
    dim3 grid(H / TH, nimg);              // (8, 128) = 1024 CTAs
    box9_kernel<<<grid, NT>>>(x, out);
}